// round 6
// baseline (speedup 1.0000x reference)
#include <cuda_runtime.h>
#include <math.h>

#define H 64
#define W 64
#define C 256
#define P 7
#define NUM_ROIS 256
#define FC (W * C)   // floats per x-row (16384)

__device__ __forceinline__ float4 fmax4(float4 a, float4 b) {
    a.x = fmaxf(a.x, b.x);
    a.y = fmaxf(a.y, b.y);
    a.z = fmaxf(a.z, b.z);
    a.w = fmaxf(a.w, b.w);
    return a;
}

// Block = (roi, i), 224 threads = 7 warps; warp j computes y-bin j.
// Lane l owns channel quads c0 = l*4 and c0+128 (both warp loads are fully
// coalesced 512B). y loop: ylen/2 clean pairs + uniform odd tail (no
// duplicate loads, no per-iteration clamping).
__global__ __launch_bounds__(224, 6) void roi_pool_kernel(
    const float* __restrict__ feat,   // (H, W, C)
    const float* __restrict__ rois,   // (NUM_ROIS, 4) = x1,y1,x2,y2
    float* __restrict__ out)          // (NUM_ROIS, P, P, C)
{
    const int b = blockIdx.x;         // r*P + i
    const int r = b / P;
    const int i = b - r * P;

    const int j    = (int)threadIdx.x >> 5;   // warp id = y-bin (0..6)
    const int lane = (int)threadIdx.x & 31;
    const int c0   = lane << 2;               // first channel quad

    const float x1 = __ldg(&rois[r * 4 + 0]);
    const float y1 = __ldg(&rois[r * 4 + 1]);
    const float x2 = __ldg(&rois[r * 4 + 2]);
    const float y2 = __ldg(&rois[r * 4 + 3]);

    // x (H) bin bounds — exact reference math; in-range for 0<=x1<x2<=1.
    const int lox   = (int)floorf(x1 * (float)H);
    const int hix   = (int)ceilf(x2 * (float)H);
    const int spanx = max(hix - lox, 1);
    const int xs    = lox + (i * spanx) / P;
    const int xe    = lox + ((i + 1) * spanx + (P - 1)) / P;
    const int xlen  = max(xe - xs, 1);

    // y (W) bin bounds for this warp's j.
    const int loy   = (int)floorf(y1 * (float)W);
    const int hiy   = (int)ceilf(y2 * (float)W);
    const int spany = max(hiy - loy, 1);
    const int ys    = loy + (j * spany) / P;
    const int ye    = loy + ((j + 1) * spany + (P - 1)) / P;
    const int ylen  = max(ye - ys, 1);

    const int npairs = ylen >> 1;       // full y pairs
    const int tailo  = (ylen & 1) ? (npairs * 2) * C : -1;  // tail y offset or -1

    const float NEG = -INFINITY;
    float4 aL = make_float4(NEG, NEG, NEG, NEG);
    float4 aH = aL;

    const float* rowp = feat + (size_t)xs * FC + (size_t)ys * C + c0;

    for (int sx = 0; sx < xlen; ++sx) {
        const float* p = rowp;
        for (int sp = 0; sp < npairs; ++sp) {
            const float4 vL0 = *reinterpret_cast<const float4*>(p);
            const float4 vH0 = *reinterpret_cast<const float4*>(p + 128);
            const float4 vL1 = *reinterpret_cast<const float4*>(p + C);
            const float4 vH1 = *reinterpret_cast<const float4*>(p + C + 128);
            aL = fmax4(aL, vL0);
            aH = fmax4(aH, vH0);
            aL = fmax4(aL, vL1);
            aH = fmax4(aH, vH1);
            p += 2 * C;
        }
        if (tailo >= 0) {   // warp-uniform: single real tail element
            const float* t = rowp + tailo;
            const float4 vL = *reinterpret_cast<const float4*>(t);
            const float4 vH = *reinterpret_cast<const float4*>(t + 128);
            aL = fmax4(aL, vL);
            aH = fmax4(aH, vH);
        }
        rowp += FC;
    }

    float* op = out + (((size_t)(r * P + i) * P + j) * C) + c0;
    *reinterpret_cast<float4*>(op)       = aL;
    *reinterpret_cast<float4*>(op + 128) = aH;
}

extern "C" void kernel_launch(void* const* d_in, const int* in_sizes, int n_in,
                              void* d_out, int out_size) {
    const float* feat = (const float*)d_in[0];
    const float* rois = (const float*)d_in[1];
    if (n_in >= 2 && in_sizes[0] == NUM_ROIS * 4 && in_sizes[1] == H * W * C) {
        feat = (const float*)d_in[1];
        rois = (const float*)d_in[0];
    }
    float* out = (float*)d_out;

    roi_pool_kernel<<<NUM_ROIS * P, 224>>>(feat, rois, out);
}